// round 15
// baseline (speedup 1.0000x reference)
#include <cuda_runtime.h>
#include <cstdint>

// Permutation: out[b,i,j,W,p,q] = x[b, 2i+p, 2j+q, W]   (k=2 unfold repack)
// x: (16, 64, 224, 224) fp32 -> pure streaming permutation, HBM-bound.
//
// R15: the one untested end-combination — LDG.128 loads (best measured
// read pattern, MLP=4 front-batched) + single 28672B cp.async.bulk store
// (best measured write pattern: R5/R7 TMA-out had the top DRAM%).
// 1D bulk needs LINEAR smem, so the interleave runs in two conflict-free
// smem passes with a register hold:
//   1. LDG.128 x4 -> swizzled STS (f = 4*tid+m, conflict-free via XOR)
//   2. sync; LDS drain-order (swizzled, stride-1 -> conflict-free) to regs
//   3. sync; STS linear at the same drain indices (stride-1, conflict-free)
//   4. fence.proxy.async; one cp.async.bulk S->G of 28672B
// 8 segments/block, 448 threads, 7168 blocks, smem 28672B (4 blocks/SM).

#define H 224
#define W_DIM 224
#define C 64
#define JN 112          // h/2
#define IN 32           // c/2
#define W4 56           // W_DIM/4 float4 per row
#define SEGB 8          // segments per block
#define THREADS 448     // SEGB * W4
#define GRID 7168       // 57344 / SEGB
#define NF4 (SEGB * W_DIM)   // 1792 float4 per block

__device__ __forceinline__ int sw(int f) { return f ^ ((f >> 3) & 7); }

__device__ __forceinline__ uint32_t smem_u32(const void* p) {
    return (uint32_t)__cvta_generic_to_shared(p);
}

__global__ void __launch_bounds__(THREADS) KernelActivation_perm15(
    const float4* __restrict__ x4, float4* __restrict__ out4)
{
    __shared__ __align__(16) float4 s[NF4];   // 28672 B

    const int tid  = threadIdx.x;
    const int sl   = tid / W4;           // 0..7 local segment
    const int wg   = tid % W4;           // 0..55 float4 group in row
    const int seg0 = blockIdx.x * SEGB;
    const int seg  = seg0 + sl;

    const int j = seg % JN;
    const int t = seg / JN;
    const int i = t & (IN - 1);
    const int b = t >> 5;

    // x[b, 2i+p, 2j+q, :] rows (float4 units)
    const int base = ((b * C + 2 * i) * H + 2 * j) * W4 + wg;

    const float4 r00 = __ldcs(&x4[base]);                 // p=0 q=0
    const float4 r01 = __ldcs(&x4[base + W4]);            // p=0 q=1
    const float4 r10 = __ldcs(&x4[base + H * W4]);        // p=1 q=0
    const float4 r11 = __ldcs(&x4[base + H * W4 + W4]);   // p=1 q=1

    // pass 1: swizzled STS (f = 4*tid + m) -> conflict-free
    const int f0 = 4 * tid;
    s[sw(f0 + 0)] = make_float4(r00.x, r01.x, r10.x, r11.x);
    s[sw(f0 + 1)] = make_float4(r00.y, r01.y, r10.y, r11.y);
    s[sw(f0 + 2)] = make_float4(r00.z, r01.z, r10.z, r11.z);
    s[sw(f0 + 3)] = make_float4(r00.w, r01.w, r10.w, r11.w);

    __syncthreads();

    // pass 2: drain-order LDS (swizzled, stride-1 -> conflict-free) to regs
    float4 v[4];
#pragma unroll
    for (int m = 0; m < 4; m++) {
        v[m] = s[sw(m * THREADS + tid)];
    }

    __syncthreads();

    // pass 3: linear STS at the drain indices (stride-1, conflict-free)
#pragma unroll
    for (int m = 0; m < 4; m++) {
        s[m * THREADS + tid] = v[m];
    }

    asm volatile("fence.proxy.async.shared::cta;" ::: "memory");
    __syncthreads();

    // single 28672B bulk store of the linear output block
    if (tid == 0) {
        char* dst = (char*)(out4 + (long)seg0 * W_DIM);
        asm volatile(
            "cp.async.bulk.global.shared::cta.bulk_group [%0], [%1], %2;"
            :: "l"(dst), "r"(smem_u32(s)), "r"((uint32_t)(NF4 * 16)) : "memory");
        asm volatile("cp.async.bulk.commit_group;" ::: "memory");
        asm volatile("cp.async.bulk.wait_group 0;" ::: "memory");
    }
}

extern "C" void kernel_launch(void* const* d_in, const int* in_sizes, int n_in,
                              void* d_out, int out_size)
{
    const float4* x4 = (const float4*)d_in[0];
    float4* out4 = (float4*)d_out;
    KernelActivation_perm15<<<GRID, THREADS>>>(x4, out4);
}

// round 16
// speedup vs baseline: 1.0204x; 1.0204x over previous
#include <cuda_runtime.h>

// Permutation: out[b,i,j,W,p,q] = x[b, 2i+p, 2j+q, W]   (k=2 unfold repack)
// x: (16, 64, 224, 224) fp32 -> pure streaming permutation, HBM-bound.
//
// FINAL KERNEL (R9; best wall 63.5us, confirmed across 3 runs of a
// 16-bench series converged at the B300 1:1 R/W HBM ceiling ~6.5 TB/s).
//
// Structure:
//  - 8 segments per block (seg = b*32*112 + i*112 + j), 448 threads,
//    one-shot grid of 7168 blocks (self-balancing waves)
//  - loads : 4x LDG.128 per thread, front-batched (MLP=4), each warp
//            instruction a contiguous 512B run; __ldcs streaming hint
//  - smem  : XOR swizzle g(f) = f ^ ((f>>3)&7) in float4 units —
//            conflict-free for BOTH the stride-4 STS interleave
//            (f = 4*tid+m) and the stride-1 LDS drain; the 28KB buffer
//            decouples the read stream from the write stream
//  - stores: contiguous 28672B run per block, STG.128 + __stcs
//
// Measured and rejected: TMA bulk in/out/both (wall neutral-to-worse;
// occupancy + wait_group tail costs), persistent grid (wave imbalance at
// 6 blocks/SM), default write-back stores, ld.global L2::256B hints,
// __launch_bounds__ forced residency, smem-free shfl quad-transpose
// (MLP collapse, +4us). DRAM-active pinned at 75-79% for every variant:
// the residual is HBM read/write bus-turnaround, not kernel-addressable.

#define H 224
#define W_DIM 224
#define C 64
#define JN 112          // h/2
#define IN 32           // c/2
#define W4 56           // W_DIM/4 float4 per row
#define SEGB 8          // segments per block
#define THREADS 448     // SEGB * W4
#define GRID 7168       // 57344 / SEGB

__device__ __forceinline__ int sw(int f) { return f ^ ((f >> 3) & 7); }

__global__ void __launch_bounds__(THREADS) KernelActivation_final(
    const float4* __restrict__ x4, float4* __restrict__ out4)
{
    __shared__ float4 s[SEGB * W_DIM];   // 28672 B

    const int tid  = threadIdx.x;
    const int sl   = tid / W4;           // 0..7 local segment
    const int wg   = tid % W4;           // 0..55 float4 group in row
    const int seg0 = blockIdx.x * SEGB;
    const int seg  = seg0 + sl;

    const int j = seg % JN;
    const int t = seg / JN;
    const int i = t & (IN - 1);
    const int b = t >> 5;

    // x[b, 2i+p, 2j+q, :] rows (float4 units)
    const int base = ((b * C + 2 * i) * H + 2 * j) * W4 + wg;

    const float4 r00 = __ldcs(&x4[base]);                 // p=0 q=0
    const float4 r01 = __ldcs(&x4[base + W4]);            // p=0 q=1
    const float4 r10 = __ldcs(&x4[base + H * W4]);        // p=1 q=0
    const float4 r11 = __ldcs(&x4[base + H * W4 + W4]);   // p=1 q=1

    // STS: f = 4*tid + m, swizzled -> conflict-free
    const int f0 = 4 * tid;
    s[sw(f0 + 0)] = make_float4(r00.x, r01.x, r10.x, r11.x);
    s[sw(f0 + 1)] = make_float4(r00.y, r01.y, r10.y, r11.y);
    s[sw(f0 + 2)] = make_float4(r00.z, r01.z, r10.z, r11.z);
    s[sw(f0 + 3)] = make_float4(r00.w, r01.w, r10.w, r11.w);

    __syncthreads();

    // drain: contiguous 28672B block store, LDS swizzled -> conflict-free
    float4* dst = &out4[(long)seg0 * W_DIM];
#pragma unroll
    for (int m = 0; m < 4; m++) {
        const int f = m * THREADS + tid;
        __stcs(&dst[f], s[sw(f)]);
    }
}

extern "C" void kernel_launch(void* const* d_in, const int* in_sizes, int n_in,
                              void* d_out, int out_size)
{
    const float4* x4 = (const float4*)d_in[0];
    float4* out4 = (float4*)d_out;
    KernelActivation_final<<<GRID, THREADS>>>(x4, out4);
}

// round 17
// speedup vs baseline: 1.0240x; 1.0035x over previous
#include <cuda_runtime.h>

// Permutation: out[b,i,j,W,p,q] = x[b, 2i+p, 2j+q, W]   (k=2 unfold repack)
// x: (16, 64, 224, 224) fp32 -> pure streaming permutation, HBM-bound.
//
// R17: MLP-depth probe. Same proven structure as R9 (8 segments/block,
// XOR-swizzled conflict-free smem, LDG.128 in / STG.128 out, streaming
// hints) but 224 threads with each thread owning TWO segments -> 8
// front-batched LDG.128 per thread (MLP_p1 = 8 vs 4). Deeper per-warp
// read queue lets the DRAM scheduler gang more row-hits between R/W bus
// turnarounds. All global/warp access shapes identical to R9.

#define H 224
#define W_DIM 224
#define C 64
#define JN 112          // h/2
#define IN 32           // c/2
#define W4 56           // W_DIM/4 float4 per row
#define SEGB 8          // segments per block
#define THREADS 224     // each thread owns 2 segments (sl, sl+4)
#define GRID 7168       // 57344 / SEGB

__device__ __forceinline__ int sw(int f) { return f ^ ((f >> 3) & 7); }

__global__ void __launch_bounds__(THREADS) KernelActivation_perm17(
    const float4* __restrict__ x4, float4* __restrict__ out4)
{
    __shared__ float4 s[SEGB * W_DIM];   // 28672 B

    const int tid  = threadIdx.x;
    const int sl   = tid / W4;           // 0..3 (first segment of the pair)
    const int wg   = tid % W4;           // 0..55 float4 group in row
    const int seg0 = blockIdx.x * SEGB;

    // two segments per thread: sl and sl+4
    int base[2];
#pragma unroll
    for (int h = 0; h < 2; h++) {
        const int seg = seg0 + sl + 4 * h;
        const int j = seg % JN;
        const int t = seg / JN;
        const int i = t & (IN - 1);
        const int b = t >> 5;
        base[h] = ((b * C + 2 * i) * H + 2 * j) * W4 + wg;
    }

    // front-batched 8x LDG.128 (MLP_p1 = 8)
    float4 r[2][4];
#pragma unroll
    for (int h = 0; h < 2; h++) {
        r[h][0] = __ldcs(&x4[base[h]]);                 // p=0 q=0
        r[h][1] = __ldcs(&x4[base[h] + W4]);            // p=0 q=1
        r[h][2] = __ldcs(&x4[base[h] + H * W4]);        // p=1 q=0
        r[h][3] = __ldcs(&x4[base[h] + H * W4 + W4]);   // p=1 q=1
    }

    // STS: for each half, f = 4*(thread's slot in that half) + m, swizzled
#pragma unroll
    for (int h = 0; h < 2; h++) {
        const int f0 = 4 * ((sl + 4 * h) * W4 + wg);
        s[sw(f0 + 0)] = make_float4(r[h][0].x, r[h][1].x, r[h][2].x, r[h][3].x);
        s[sw(f0 + 1)] = make_float4(r[h][0].y, r[h][1].y, r[h][2].y, r[h][3].y);
        s[sw(f0 + 2)] = make_float4(r[h][0].z, r[h][1].z, r[h][2].z, r[h][3].z);
        s[sw(f0 + 3)] = make_float4(r[h][0].w, r[h][1].w, r[h][2].w, r[h][3].w);
    }

    __syncthreads();

    // drain: contiguous 28672B block store, LDS swizzled -> conflict-free
    float4* dst = &out4[(long)seg0 * W_DIM];
#pragma unroll
    for (int m = 0; m < 8; m++) {
        const int f = m * THREADS + tid;
        __stcs(&dst[f], s[sw(f)]);
    }
}

extern "C" void kernel_launch(void* const* d_in, const int* in_sizes, int n_in,
                              void* d_out, int out_size)
{
    const float4* x4 = (const float4*)d_in[0];
    float4* out4 = (float4*)d_out;
    KernelActivation_perm17<<<GRID, THREADS>>>(x4, out4);
}